// round 8
// baseline (speedup 1.0000x reference)
#include <cuda_runtime.h>
#include <cuda_bf16.h>
#include <math.h>
#include <stdint.h>

// ---------------- problem constants ----------------
#define B_SZ   1024
#define HID    512
#define INSZ   64
#define TSTEPS 256
#define GATES  2048              // 4*HID
#define KTOT   576               // INSZ + HID
#define XCOLS  (TSTEPS * INSZ)   // 16384

// ---------------- GEMM tiling ----------------
#define BM 128
#define BN 128
#define KTILE 64                 // 64 bf16 = 128 bytes per row
#define NJOBS 18                 // interleaved: even=hi(sub), odd=lo(sub)
#define NROWCTA 16               // CTAs per row group (same blockIdx.y)

// SW128 swizzle (Swizzle<3,4,3>) on byte offsets within a tile
#define SWZ(o) ((o) ^ (((o) >> 3) & 0x70))

// dynamic smem layout (all tile bases 1024-aligned)
#define SOFF_BH    0                         // 9 x 16384 = 147456
#define SOFF_A     147456                    // 3 x 16384 (triple buffer)
#define SOFF_BL    (SOFF_A + 49152)          // 2 x 16384
#define SMEM_TOTAL (SOFF_BL + 32768)         // 229376

// ---------------- device scratch (no allocs allowed) ----------------
static __device__ __align__(256) __nv_bfloat16 g_xh[(size_t)B_SZ * XCOLS];
static __device__ __align__(256) __nv_bfloat16 g_xl[(size_t)B_SZ * XCOLS];
static __device__ __align__(256) __nv_bfloat16 g_Bh[GATES * KTOT];   // packed col = n*4+g
static __device__ __align__(256) __nv_bfloat16 g_Bl[GATES * KTOT];
static __device__ float        g_bias[GATES];
static __device__ __align__(256) __nv_bfloat16 g_hh[2][B_SZ * HID];
static __device__ __align__(256) __nv_bfloat16 g_hl[2][B_SZ * HID];
// per-row-group tickets, 128B apart; reset to 0 at the start of every launch
static __device__ unsigned long long g_row_ticket[8 * 16];

// ---------------- PTX helpers ----------------
__device__ __forceinline__ uint32_t smem_u32(const void* p) {
    uint32_t a;
    asm("{ .reg .u64 t; cvta.to.shared.u64 t, %1; cvt.u32.u64 %0, t; }"
        : "=r"(a) : "l"(p));
    return a;
}

__device__ __forceinline__ void cp16(uint32_t dst, const void* src) {
    asm volatile("cp.async.cg.shared.global [%0], [%1], 16;"
                 :: "r"(dst), "l"(src));
}
__device__ __forceinline__ void cp_commit() {
    asm volatile("cp.async.commit_group;" ::: "memory");
}
template<int N>
__device__ __forceinline__ void cp_wait() {
    asm volatile("cp.async.wait_group %0;" :: "n"(N) : "memory");
}

__device__ __forceinline__ void ldsm4(uint32_t* r, uint32_t addr) {
    asm volatile("ldmatrix.sync.aligned.m8n8.x4.shared.b16 {%0,%1,%2,%3}, [%4];"
                 : "=r"(r[0]), "=r"(r[1]), "=r"(r[2]), "=r"(r[3]) : "r"(addr));
}

__device__ __forceinline__ void mma16816(float* c, const uint32_t* a, const uint32_t* b) {
    asm volatile(
        "mma.sync.aligned.m16n8k16.row.col.f32.bf16.bf16.f32 "
        "{%0,%1,%2,%3}, {%4,%5,%6,%7}, {%8,%9}, {%0,%1,%2,%3};"
        : "+f"(c[0]), "+f"(c[1]), "+f"(c[2]), "+f"(c[3])
        : "r"(a[0]), "r"(a[1]), "r"(a[2]), "r"(a[3]), "r"(b[0]), "r"(b[1]));
}

__device__ __forceinline__ float fsig(float x) {
    float e = __expf(-x);
    return __fdividef(1.f, 1.f + e);
}
__device__ __forceinline__ float ftanh(float x) {
    return 2.f * fsig(2.f * x) - 1.f;
}

// ---------------- prepack kernels ----------------
__global__ void prepack_x_kernel(const float* __restrict__ x) {
    size_t idx = (size_t)blockIdx.x * blockDim.x + threadIdx.x;
    size_t stride = (size_t)gridDim.x * blockDim.x;
    const size_t total = (size_t)B_SZ * XCOLS;
    for (size_t i = idx; i < total; i += stride) {
        float v = x[i];
        __nv_bfloat16 hi = __float2bfloat16(v);
        g_xh[i] = hi;
        g_xl[i] = __float2bfloat16(v - __bfloat162float(hi));
    }
}

__global__ void prepack_w_kernel(const float* __restrict__ W_ih,
                                 const float* __restrict__ W_hh,
                                 const float* __restrict__ b_ih,
                                 const float* __restrict__ b_hh) {
    int idx = blockIdx.x * blockDim.x + threadIdx.x;
    int stride = gridDim.x * blockDim.x;
    const int total = GATES * KTOT;
    for (int i = idx; i < total; i += stride) {
        int col = i / KTOT;
        int k   = i - col * KTOT;
        int n = col >> 2, g = col & 3;
        int row = g * HID + n;
        float v = (k < INSZ) ? W_ih[row * INSZ + k] : W_hh[row * HID + (k - INSZ)];
        __nv_bfloat16 hi = __float2bfloat16(v);
        g_Bh[i] = hi;
        g_Bl[i] = __float2bfloat16(v - __bfloat162float(hi));
    }
    for (int i = idx; i < GATES; i += stride) {
        int n = i >> 2, g = i & 3;
        int row = g * HID + n;
        g_bias[i] = b_ih[row] + b_hh[row];
    }
}

__global__ void init_state_kernel(const float* __restrict__ h0) {
    int idx = blockIdx.x * blockDim.x + threadIdx.x;
    int stride = gridDim.x * blockDim.x;
    for (int i = idx; i < B_SZ * HID; i += stride) {
        float h = h0[i];
        __nv_bfloat16 hi = __float2bfloat16(h);
        g_hh[0][i] = hi;
        g_hl[0][i] = __float2bfloat16(h - __bfloat162float(hi));
    }
}

__global__ void reset_tickets_kernel() {
    if (threadIdx.x < 8 * 16) g_row_ticket[threadIdx.x] = 0ULL;
}

// ---------------- persistent LSTM kernel (256 threads, 8 fat warps) ----------------
// warp grid: 2 (M) x 4 (N); warp tile 64 x 32 -> bytes/MAC 0.094 (was 0.125)
__global__ __launch_bounds__(256, 1)
void lstm_persistent(const float* __restrict__ c0g)
{
    extern __shared__ char smem[];
    const uint32_t sbase = smem_u32(smem);
    const int tid  = threadIdx.x;
    const int wid  = tid >> 5;
    const int lane = tid & 31;
    const int row0 = blockIdx.y * BM;   // batch base
    const int col0 = blockIdx.x * BN;   // packed gate col base
    const int wm = wid >> 2;            // 0..1 (M group, 64 rows)
    const int wn = wid & 3;             // 0..3 (N group, 32 cols)

    // loader mapping: 256 threads cover 128 rows x 128B (64B per thread)
    const int r     = tid >> 1;
    const int halfe = (tid & 1) * 32;              // element offset
    const uint32_t rowoff = (uint32_t)r * 128 + (tid & 1) * 64;

    // ---- load resident B_hi (9 chunks, 147KB) ----
    {
        const size_t bb = (size_t)(col0 + r) * KTOT + (size_t)halfe;
        for (int sub = 0; sub < 9; ++sub) {
            uint32_t dst = sbase + SOFF_BH + sub * 16384;
#pragma unroll
            for (int c = 0; c < 4; ++c)
                cp16(dst + SWZ(rowoff + c * 16), g_Bh + bb + sub * KTILE + c * 8);
        }
        cp_commit();
    }

    // ---- per-thread epilogue constants: c state + bias in registers ----
    const int q  = lane & 3;
    const bool ev = (q & 1) == 0;
    float creg[4][4][2];
    float bb0[4], bb1[4];
#pragma unroll
    for (int nf = 0; nf < 4; ++nf) {
        int cb = wn * 32 + nf * 8 + q * 2;
        bb0[nf] = g_bias[col0 + cb];
        bb1[nf] = g_bias[col0 + cb + 1];
#pragma unroll
        for (int mf = 0; mf < 4; ++mf)
#pragma unroll
            for (int rs = 0; rs < 2; ++rs) {
                int n = (col0 + cb) >> 2;
                int b = row0 + wm * 64 + (lane >> 2) + mf * 16 + rs * 8;
                creg[mf][nf][rs] = c0g[(size_t)b * HID + n];
            }
    }

    cp_wait<0>();
    __syncthreads();

    // fragment addressing constants
    const int lane7 = lane & 7;
    const int arow  = wm * 64 + ((lane >> 3) & 1) * 8 + lane7;   // + mf*16
    const int ach   = (lane >> 4) & 1;
    const int brow  = wn * 32 + ((lane >> 4) & 1) * 8 + lane7;   // + p*16
    const int bch   = (lane >> 3) & 1;

    const uint32_t sA0  = sbase + SOFF_A;
    const uint32_t sBL0 = sbase + SOFF_BL;

    // job jid: even = hi(sub=jid/2): A_hi x (B_hi + B_lo); odd = lo: A_lo x B_hi
    // A buffer = jid % 3 (triple); BL buffer = (jid/2) & 1 (double).
    auto issue_job = [&](int jid, int t, int buf) {
        const int sub = jid >> 1;
        const bool hi = (jid & 1) == 0;
        const __nv_bfloat16* __restrict__ Asrc;
        size_t abase;
        if (sub == 0) {   // x part (h-independent)
            Asrc  = hi ? g_xh : g_xl;
            abase = (size_t)(row0 + r) * XCOLS + (size_t)t * INSZ;
        } else {
            Asrc  = hi ? g_hh[buf] : g_hl[buf];
            abase = (size_t)(row0 + r) * HID + (size_t)(sub - 1) * KTILE;
        }
        abase += (size_t)halfe;
        const uint32_t ao = (uint32_t)(jid % 3) * 16384;
#pragma unroll
        for (int c = 0; c < 4; ++c)
            cp16(sA0 + ao + SWZ(rowoff + c * 16), Asrc + abase + c * 8);
        if (hi) {
            const size_t bbase = (size_t)(col0 + r) * KTOT
                                 + (size_t)sub * KTILE + (size_t)halfe;
            const uint32_t bo = (uint32_t)(sub & 1) * 16384;
#pragma unroll
            for (int c = 0; c < 4; ++c)
                cp16(sBL0 + bo + SWZ(rowoff + c * 16), g_Bl + bbase + c * 8);
        }
        cp_commit();
    };

    float acc[4][4][4];

    // MMA of one job on current acc
    auto mma_job = [&](int j) {
        const int sub = j >> 1;
        const bool hi = (j & 1) == 0;
        const uint32_t sA  = sA0 + (uint32_t)(j % 3) * 16384;
        const uint32_t sBH = sbase + SOFF_BH + (uint32_t)sub * 16384;
        const uint32_t sBL = sBL0 + (uint32_t)(sub & 1) * 16384;
#pragma unroll
        for (int kk = 0; kk < 4; ++kk) {
            uint32_t af[4][4];
#pragma unroll
            for (int mf = 0; mf < 4; ++mf)
                ldsm4(af[mf], sA + SWZ((uint32_t)(arow + mf * 16) * 128
                                       + (uint32_t)(kk * 2 + ach) * 16));
            {
                uint32_t bf[4][2];
#pragma unroll
                for (int p = 0; p < 2; ++p) {
                    uint32_t rr[4];
                    ldsm4(rr, sBH + SWZ((uint32_t)(brow + p * 16) * 128
                                        + (uint32_t)(kk * 2 + bch) * 16));
                    bf[p * 2 + 0][0] = rr[0]; bf[p * 2 + 0][1] = rr[1];
                    bf[p * 2 + 1][0] = rr[2]; bf[p * 2 + 1][1] = rr[3];
                }
#pragma unroll
                for (int mf = 0; mf < 4; ++mf)
#pragma unroll
                    for (int nf = 0; nf < 4; ++nf)
                        mma16816(acc[mf][nf], af[mf], bf[nf]);
            }
            if (hi) {
                uint32_t bf[4][2];
#pragma unroll
                for (int p = 0; p < 2; ++p) {
                    uint32_t rr[4];
                    ldsm4(rr, sBL + SWZ((uint32_t)(brow + p * 16) * 128
                                        + (uint32_t)(kk * 2 + bch) * 16));
                    bf[p * 2 + 0][0] = rr[0]; bf[p * 2 + 0][1] = rr[1];
                    bf[p * 2 + 1][0] = rr[2]; bf[p * 2 + 1][1] = rr[3];
                }
#pragma unroll
                for (int mf = 0; mf < 4; ++mf)
#pragma unroll
                    for (int nf = 0; nf < 4; ++nf)
                        mma16816(acc[mf][nf], af[mf], bf[nf]);
            }
        }
    };

    // prologue: x jobs of step 0
    issue_job(0, 0, 0);
    issue_job(1, 0, 0);

    for (int t = 0; t < TSTEPS; ++t) {
        const int buf  = t & 1;
        const int nbuf = buf ^ 1;

#pragma unroll
        for (int mf = 0; mf < 4; ++mf)
#pragma unroll
            for (int nf = 0; nf < 4; ++nf)
#pragma unroll
                for (int u = 0; u < 4; ++u) acc[mf][nf][u] = 0.f;

        // ---- job 0 (x hi): barrier-independent, hides the row-group spin ----
        cp_wait<1>();
        __syncthreads();
        mma_job(0);

        // ---- row-group barrier: h[t] visible (overlapped by job-0 MMA) ----
        if (t > 0 && tid == 0) {
            const unsigned long long target =
                (unsigned long long)t * (unsigned long long)NROWCTA;
            unsigned long long cur;
            unsigned long long* p = &g_row_ticket[blockIdx.y * 16];
            do {
                asm volatile("ld.acquire.gpu.u64 %0, [%1];" : "=l"(cur) : "l"(p));
            } while (cur < target);
        }
        __syncthreads();   // orders job-0 MMA before buffer reuse below

        // now safe to touch h: issue first two h jobs
        issue_job(2, t, buf);
        issue_job(3, t, buf);

        // ---- job 1 (x lo) ----
        cp_wait<2>();
        __syncthreads();
        mma_job(1);

        // ---- jobs 2..17 steady state ----
        for (int j = 2; j < NJOBS; ++j) {
            if (j == NJOBS - 1) cp_wait<0>(); else cp_wait<1>();
            __syncthreads();
            if (j + 2 < NJOBS) {
                issue_job(j + 2, t, buf);
            } else if (j == NJOBS - 1 && t + 1 < TSTEPS) {
                // pre-issue h-independent x jobs of next step
                issue_job(0, t + 1, nbuf);
                issue_job(1, t + 1, nbuf);
            }
            mma_job(j);
        }

        // ---- fused LSTM epilogue ----
#pragma unroll
        for (int mf = 0; mf < 4; ++mf) {
#pragma unroll
            for (int nf = 0; nf < 4; ++nf) {
                const int cb = wn * 32 + nf * 8 + q * 2;
#pragma unroll
                for (int rs = 0; rs < 2; ++rs) {
                    float v0 = acc[mf][nf][rs * 2 + 0] + bb0[nf];
                    float v1 = acc[mf][nf][rs * 2 + 1] + bb1[nf];
                    float x0 = ev ? fsig(v0) : ftanh(v0);
                    float x1 = fsig(v1);
                    float y0 = __shfl_xor_sync(0xffffffffu, x0, 1);
                    float y1 = __shfl_xor_sync(0xffffffffu, x1, 1);
                    if (ev) {
                        const int n = (col0 + cb) >> 2;
                        const int b = row0 + wm * 64 + (lane >> 2) + mf * 16 + rs * 8;
                        const size_t idx = (size_t)b * HID + n;
                        float cn = x1 * creg[mf][nf][rs] + x0 * y0;   // f*c + i*g
                        creg[mf][nf][rs] = cn;
                        float hn = y1 * ftanh(cn);                    // o * tanh(c)
                        __nv_bfloat16 hhi = __float2bfloat16(hn);
                        g_hh[nbuf][idx] = hhi;
                        g_hl[nbuf][idx] = __float2bfloat16(hn - __bfloat162float(hhi));
                    }
                }
            }
        }

        // post arrival for next step's row barrier (release semantics)
        if (t + 1 < TSTEPS) {
            __syncthreads();
            if (tid == 0) {
                unsigned long long one = 1ULL;
                asm volatile("red.release.gpu.global.add.u64 [%0], %1;"
                             :: "l"(&g_row_ticket[blockIdx.y * 16]), "l"(one)
                             : "memory");
            }
        }
    }
}

// ---------------- final linear ----------------
__global__ void final_linear_kernel(const float* __restrict__ W_lin,
                                    const float* __restrict__ b_lin,
                                    float* __restrict__ out, int buf)
{
    int b = blockIdx.x;
    int w = threadIdx.y;      // 0..9
    int lane = threadIdx.x;   // 0..31
    const __nv_bfloat16* hh = g_hh[buf] + (size_t)b * HID;
    const __nv_bfloat16* hl = g_hl[buf] + (size_t)b * HID;
    const float* wl = W_lin + (size_t)w * HID;
    float s = 0.f;
#pragma unroll 4
    for (int k = lane; k < HID; k += 32) {
        float h = __bfloat162float(hh[k]) + __bfloat162float(hl[k]);
        s += h * wl[k];
    }
#pragma unroll
    for (int off = 16; off; off >>= 1)
        s += __shfl_down_sync(0xffffffffu, s, off);
    if (lane == 0)
        out[b * 10 + w] = s + b_lin[w];
}

// ---------------- launch ----------------
extern "C" void kernel_launch(void* const* d_in, const int* in_sizes, int n_in,
                              void* d_out, int out_size)
{
    const float* x     = (const float*)d_in[0];
    const float* h0    = (const float*)d_in[1];
    const float* c0    = (const float*)d_in[2];
    const float* W_ih  = (const float*)d_in[3];
    const float* W_hh  = (const float*)d_in[4];
    const float* b_ih  = (const float*)d_in[5];
    const float* b_hh  = (const float*)d_in[6];
    const float* W_lin = (const float*)d_in[7];
    const float* b_lin = (const float*)d_in[8];
    float* out = (float*)d_out;

    cudaFuncSetAttribute(lstm_persistent,
                         cudaFuncAttributeMaxDynamicSharedMemorySize, SMEM_TOTAL);

    reset_tickets_kernel<<<1, 128>>>();
    prepack_x_kernel<<<2048, 256>>>(x);
    prepack_w_kernel<<<1024, 256>>>(W_ih, W_hh, b_ih, b_hh);
    init_state_kernel<<<512, 512>>>(h0);

    dim3 grid(GATES / BN, B_SZ / BM);   // 16 x 8 = 128 CTAs (all resident)
    lstm_persistent<<<grid, 256, SMEM_TOTAL>>>(c0);

    // 256 steps -> final h is in buffer 0
    final_linear_kernel<<<B_SZ, dim3(32, 10)>>>(W_lin, b_lin, out, 0);
}

// round 9
// speedup vs baseline: 1.0620x; 1.0620x over previous
#include <cuda_runtime.h>
#include <cuda_bf16.h>
#include <math.h>
#include <stdint.h>

// ---------------- problem constants ----------------
#define B_SZ   1024
#define HID    512
#define INSZ   64
#define TSTEPS 256
#define GATES  2048              // 4*HID
#define KTOT   576               // INSZ + HID
#define XCOLS  (TSTEPS * INSZ)   // 16384

// ---------------- GEMM tiling ----------------
#define BM 128
#define BN 128
#define KTILE 64                 // 64 bf16 = 128 bytes per row
#define NJOBS 18                 // interleaved: even=hi(sub), odd=lo(sub)
#define NROWCTA 16               // CTAs per row group (same blockIdx.y)

// SW128 swizzle (Swizzle<3,4,3>) on byte offsets within a tile
#define SWZ(o) ((o) ^ (((o) >> 3) & 0x70))

// dynamic smem layout (all tile bases 1024-aligned)
#define SOFF_BH    0                         // 9 x 16384 = 147456
#define SOFF_A     147456                    // 3 x 16384 (triple buffer)
#define SOFF_BL    (SOFF_A + 49152)          // 2 x 16384
#define SMEM_TOTAL (SOFF_BL + 32768)         // 229376

// ---------------- device scratch (no allocs allowed) ----------------
static __device__ __align__(256) __nv_bfloat16 g_xh[(size_t)B_SZ * XCOLS];
static __device__ __align__(256) __nv_bfloat16 g_xl[(size_t)B_SZ * XCOLS];
static __device__ __align__(256) __nv_bfloat16 g_Bh[GATES * KTOT];   // packed col = n*4+g
static __device__ __align__(256) __nv_bfloat16 g_Bl[GATES * KTOT];
static __device__ float        g_bias[GATES];
static __device__ __align__(256) __nv_bfloat16 g_hh[2][B_SZ * HID];
static __device__ __align__(256) __nv_bfloat16 g_hl[2][B_SZ * HID];
// per-row-group tickets, 128B apart; reset to 0 at the start of every launch
static __device__ unsigned long long g_row_ticket[8 * 16];

// ---------------- PTX helpers ----------------
__device__ __forceinline__ uint32_t smem_u32(const void* p) {
    uint32_t a;
    asm("{ .reg .u64 t; cvta.to.shared.u64 t, %1; cvt.u32.u64 %0, t; }"
        : "=r"(a) : "l"(p));
    return a;
}

__device__ __forceinline__ void cp16(uint32_t dst, const void* src) {
    asm volatile("cp.async.cg.shared.global [%0], [%1], 16;"
                 :: "r"(dst), "l"(src));
}
__device__ __forceinline__ void cp_commit() {
    asm volatile("cp.async.commit_group;" ::: "memory");
}
template<int N>
__device__ __forceinline__ void cp_wait() {
    asm volatile("cp.async.wait_group %0;" :: "n"(N) : "memory");
}

__device__ __forceinline__ void ldsm4(uint32_t* r, uint32_t addr) {
    asm volatile("ldmatrix.sync.aligned.m8n8.x4.shared.b16 {%0,%1,%2,%3}, [%4];"
                 : "=r"(r[0]), "=r"(r[1]), "=r"(r[2]), "=r"(r[3]) : "r"(addr));
}

__device__ __forceinline__ void mma16816(float* c, const uint32_t* a, const uint32_t* b) {
    asm volatile(
        "mma.sync.aligned.m16n8k16.row.col.f32.bf16.bf16.f32 "
        "{%0,%1,%2,%3}, {%4,%5,%6,%7}, {%8,%9}, {%0,%1,%2,%3};"
        : "+f"(c[0]), "+f"(c[1]), "+f"(c[2]), "+f"(c[3])
        : "r"(a[0]), "r"(a[1]), "r"(a[2]), "r"(a[3]), "r"(b[0]), "r"(b[1]));
}

__device__ __forceinline__ float fsig(float x) {
    float e = __expf(-x);
    return __fdividef(1.f, 1.f + e);
}
__device__ __forceinline__ float ftanh(float x) {
    return 2.f * fsig(2.f * x) - 1.f;
}

// ---------------- prepack kernels ----------------
__global__ void prepack_x_kernel(const float* __restrict__ x) {
    size_t idx = (size_t)blockIdx.x * blockDim.x + threadIdx.x;
    size_t stride = (size_t)gridDim.x * blockDim.x;
    const size_t total = (size_t)B_SZ * XCOLS;
    for (size_t i = idx; i < total; i += stride) {
        float v = x[i];
        __nv_bfloat16 hi = __float2bfloat16(v);
        g_xh[i] = hi;
        g_xl[i] = __float2bfloat16(v - __bfloat162float(hi));
    }
}

__global__ void prepack_w_kernel(const float* __restrict__ W_ih,
                                 const float* __restrict__ W_hh,
                                 const float* __restrict__ b_ih,
                                 const float* __restrict__ b_hh) {
    int idx = blockIdx.x * blockDim.x + threadIdx.x;
    int stride = gridDim.x * blockDim.x;
    const int total = GATES * KTOT;
    for (int i = idx; i < total; i += stride) {
        int col = i / KTOT;
        int k   = i - col * KTOT;
        int n = col >> 2, g = col & 3;
        int row = g * HID + n;
        float v = (k < INSZ) ? W_ih[row * INSZ + k] : W_hh[row * HID + (k - INSZ)];
        __nv_bfloat16 hi = __float2bfloat16(v);
        g_Bh[i] = hi;
        g_Bl[i] = __float2bfloat16(v - __bfloat162float(hi));
    }
    for (int i = idx; i < GATES; i += stride) {
        int n = i >> 2, g = i & 3;
        int row = g * HID + n;
        g_bias[i] = b_ih[row] + b_hh[row];
    }
}

__global__ void init_state_kernel(const float* __restrict__ h0) {
    int idx = blockIdx.x * blockDim.x + threadIdx.x;
    int stride = gridDim.x * blockDim.x;
    for (int i = idx; i < B_SZ * HID; i += stride) {
        float h = h0[i];
        __nv_bfloat16 hi = __float2bfloat16(h);
        g_hh[0][i] = hi;
        g_hl[0][i] = __float2bfloat16(h - __bfloat162float(hi));
    }
}

__global__ void reset_tickets_kernel() {
    if (threadIdx.x < 8 * 16) g_row_ticket[threadIdx.x] = 0ULL;
}

// ---------------- persistent LSTM kernel (512 threads) ----------------
__global__ __launch_bounds__(512, 1)
void lstm_persistent(const float* __restrict__ c0g)
{
    extern __shared__ char smem[];
    const uint32_t sbase = smem_u32(smem);
    const int tid  = threadIdx.x;
    const int wid  = tid >> 5;
    const int lane = tid & 31;
    const int row0 = blockIdx.y * BM;   // batch base
    const int col0 = blockIdx.x * BN;   // packed gate col base
    const int wm = wid & 3;             // 0..3 (M)
    const int wn = wid >> 2;            // 0..3 (N)

    // loader mapping: 512 threads cover 128 rows x 128B (32B per thread)
    const int r     = tid >> 2;
    const int quart = tid & 3;
    const uint32_t rowoff = (uint32_t)r * 128 + (uint32_t)quart * 32;

    // ---- load resident B_hi (9 chunks, 147KB) ----
    {
        const size_t bb = (size_t)(col0 + r) * KTOT + (size_t)quart * 16;
        for (int sub = 0; sub < 9; ++sub) {
            uint32_t dst = sbase + SOFF_BH + sub * 16384;
#pragma unroll
            for (int c = 0; c < 2; ++c)
                cp16(dst + SWZ(rowoff + c * 16), g_Bh + bb + sub * KTILE + c * 8);
        }
        cp_commit();
    }

    // ---- per-thread epilogue constants: c state + bias in registers ----
    const int q  = lane & 3;
    const bool ev = (q & 1) == 0;
    float creg[2][4][2];
    float bb0[4], bb1[4];
#pragma unroll
    for (int nf = 0; nf < 4; ++nf) {
        int cb = wn * 32 + nf * 8 + q * 2;
        bb0[nf] = g_bias[col0 + cb];
        bb1[nf] = g_bias[col0 + cb + 1];
#pragma unroll
        for (int mf = 0; mf < 2; ++mf)
#pragma unroll
            for (int rs = 0; rs < 2; ++rs) {
                int n = (col0 + cb) >> 2;
                int b = row0 + wm * 32 + (lane >> 2) + mf * 16 + rs * 8;
                creg[mf][nf][rs] = c0g[(size_t)b * HID + n];
            }
    }

    cp_wait<0>();
    __syncthreads();

    // fragment addressing constants
    const int lane7 = lane & 7;
    const int arow  = wm * 32 + ((lane >> 3) & 1) * 8 + lane7;   // + mf*16
    const int ach   = (lane >> 4) & 1;
    const int brow  = wn * 32 + ((lane >> 4) & 1) * 8 + lane7;   // + p*16
    const int bch   = (lane >> 3) & 1;

    const uint32_t sA0  = sbase + SOFF_A;
    const uint32_t sBL0 = sbase + SOFF_BL;

    // job jid: even = hi(sub=jid/2): A_hi x (B_hi + B_lo); odd = lo: A_lo x B_hi
    // A buffer = jid % 3 (triple); BL buffer = (jid/2) & 1 (double).
    auto issue_job = [&](int jid, int t, int buf) {
        const int sub = jid >> 1;
        const bool hi = (jid & 1) == 0;
        const __nv_bfloat16* __restrict__ Asrc;
        size_t abase;
        if (sub == 0) {   // x part (h-independent)
            Asrc  = hi ? g_xh : g_xl;
            abase = (size_t)(row0 + r) * XCOLS + (size_t)t * INSZ;
        } else {
            Asrc  = hi ? g_hh[buf] : g_hl[buf];
            abase = (size_t)(row0 + r) * HID + (size_t)(sub - 1) * KTILE;
        }
        abase += (size_t)quart * 16;
        const uint32_t ao = (uint32_t)(jid % 3) * 16384;
#pragma unroll
        for (int c = 0; c < 2; ++c)
            cp16(sA0 + ao + SWZ(rowoff + c * 16), Asrc + abase + c * 8);
        if (hi) {
            const size_t bbase = (size_t)(col0 + r) * KTOT
                                 + (size_t)sub * KTILE + (size_t)quart * 16;
            const uint32_t bo = (uint32_t)(sub & 1) * 16384;
#pragma unroll
            for (int c = 0; c < 2; ++c)
                cp16(sBL0 + bo + SWZ(rowoff + c * 16), g_Bl + bbase + c * 8);
        }
        cp_commit();
    };

    float acc[2][4][4];

    // fragment load helpers (one kk slice)
    auto load_af = [&](uint32_t sA, int kk, uint32_t af[2][4]) {
#pragma unroll
        for (int mf = 0; mf < 2; ++mf)
            ldsm4(af[mf], sA + SWZ((uint32_t)(arow + mf * 16) * 128
                                   + (uint32_t)(kk * 2 + ach) * 16));
    };
    auto load_bf = [&](uint32_t sB, int kk, uint32_t bf[4][2]) {
#pragma unroll
        for (int p = 0; p < 2; ++p) {
            uint32_t rr[4];
            ldsm4(rr, sB + SWZ((uint32_t)(brow + p * 16) * 128
                               + (uint32_t)(kk * 2 + bch) * 16));
            bf[p * 2 + 0][0] = rr[0]; bf[p * 2 + 0][1] = rr[1];
            bf[p * 2 + 1][0] = rr[2]; bf[p * 2 + 1][1] = rr[3];
        }
    };
    auto mma_pass = [&](uint32_t af[2][4], uint32_t bf[4][2]) {
#pragma unroll
        for (int mf = 0; mf < 2; ++mf)
#pragma unroll
            for (int nf = 0; nf < 4; ++nf)
                mma16816(acc[mf][nf], af[mf], bf[nf]);
    };

    // MMA of one job with register double-buffering across kk:
    // LDSM for kk+1 issues before the MMAs of kk drain -> LDS latency hidden.
    auto mma_job = [&](int j) {
        const int sub = j >> 1;
        const bool hi = (j & 1) == 0;
        const uint32_t sA  = sA0 + (uint32_t)(j % 3) * 16384;
        const uint32_t sBH = sbase + SOFF_BH + (uint32_t)sub * 16384;
        const uint32_t sBL = sBL0 + (uint32_t)(sub & 1) * 16384;

        uint32_t afb[2][2][4];
        uint32_t bhb[2][4][2];
        uint32_t blb[2][4][2];

        load_af(sA, 0, afb[0]);
        load_bf(sBH, 0, bhb[0]);
        if (hi) load_bf(sBL, 0, blb[0]);

#pragma unroll
        for (int kk = 0; kk < 4; ++kk) {
            const int cur = kk & 1, nxt = cur ^ 1;
            if (kk < 3) {
                load_af(sA, kk + 1, afb[nxt]);
                load_bf(sBH, kk + 1, bhb[nxt]);
                if (hi) load_bf(sBL, kk + 1, blb[nxt]);
            }
            mma_pass(afb[cur], bhb[cur]);
            if (hi) mma_pass(afb[cur], blb[cur]);
        }
    };

    // prologue: x jobs of step 0
    issue_job(0, 0, 0);
    issue_job(1, 0, 0);

    for (int t = 0; t < TSTEPS; ++t) {
        const int buf  = t & 1;
        const int nbuf = buf ^ 1;

#pragma unroll
        for (int mf = 0; mf < 2; ++mf)
#pragma unroll
            for (int nf = 0; nf < 4; ++nf)
#pragma unroll
                for (int u = 0; u < 4; ++u) acc[mf][nf][u] = 0.f;

        // ---- job 0 (x hi): barrier-independent, hides the row-group spin ----
        cp_wait<1>();
        __syncthreads();
        mma_job(0);

        // ---- row-group barrier: h[t] visible (overlapped by job-0 MMA) ----
        if (t > 0 && tid == 0) {
            const unsigned long long target =
                (unsigned long long)t * (unsigned long long)NROWCTA;
            unsigned long long cur;
            unsigned long long* p = &g_row_ticket[blockIdx.y * 16];
            do {
                asm volatile("ld.acquire.gpu.u64 %0, [%1];" : "=l"(cur) : "l"(p));
            } while (cur < target);
        }
        __syncthreads();   // orders job-0 MMA before buffer reuse below

        // now safe to touch h: issue first two h jobs
        issue_job(2, t, buf);
        issue_job(3, t, buf);

        // ---- job 1 (x lo) ----
        cp_wait<2>();
        __syncthreads();
        mma_job(1);

        // ---- jobs 2..17 steady state ----
        for (int j = 2; j < NJOBS; ++j) {
            if (j == NJOBS - 1) cp_wait<0>(); else cp_wait<1>();
            __syncthreads();
            if (j + 2 < NJOBS) {
                issue_job(j + 2, t, buf);
            } else if (j == NJOBS - 1 && t + 1 < TSTEPS) {
                // pre-issue h-independent x jobs of next step
                issue_job(0, t + 1, nbuf);
                issue_job(1, t + 1, nbuf);
            }
            mma_job(j);
        }

        // ---- fused LSTM epilogue ----
#pragma unroll
        for (int mf = 0; mf < 2; ++mf) {
#pragma unroll
            for (int nf = 0; nf < 4; ++nf) {
                const int cb = wn * 32 + nf * 8 + q * 2;
#pragma unroll
                for (int rs = 0; rs < 2; ++rs) {
                    float v0 = acc[mf][nf][rs * 2 + 0] + bb0[nf];
                    float v1 = acc[mf][nf][rs * 2 + 1] + bb1[nf];
                    float x0 = ev ? fsig(v0) : ftanh(v0);
                    float x1 = fsig(v1);
                    float y0 = __shfl_xor_sync(0xffffffffu, x0, 1);
                    float y1 = __shfl_xor_sync(0xffffffffu, x1, 1);
                    if (ev) {
                        const int n = (col0 + cb) >> 2;
                        const int b = row0 + wm * 32 + (lane >> 2) + mf * 16 + rs * 8;
                        const size_t idx = (size_t)b * HID + n;
                        float cn = x1 * creg[mf][nf][rs] + x0 * y0;   // f*c + i*g
                        creg[mf][nf][rs] = cn;
                        float hn = y1 * ftanh(cn);                    // o * tanh(c)
                        __nv_bfloat16 hhi = __float2bfloat16(hn);
                        g_hh[nbuf][idx] = hhi;
                        g_hl[nbuf][idx] = __float2bfloat16(hn - __bfloat162float(hhi));
                    }
                }
            }
        }

        // post arrival for next step's row barrier (release semantics)
        if (t + 1 < TSTEPS) {
            __syncthreads();
            if (tid == 0) {
                unsigned long long one = 1ULL;
                asm volatile("red.release.gpu.global.add.u64 [%0], %1;"
                             :: "l"(&g_row_ticket[blockIdx.y * 16]), "l"(one)
                             : "memory");
            }
        }
    }
}

// ---------------- final linear ----------------
__global__ void final_linear_kernel(const float* __restrict__ W_lin,
                                    const float* __restrict__ b_lin,
                                    float* __restrict__ out, int buf)
{
    int b = blockIdx.x;
    int w = threadIdx.y;      // 0..9
    int lane = threadIdx.x;   // 0..31
    const __nv_bfloat16* hh = g_hh[buf] + (size_t)b * HID;
    const __nv_bfloat16* hl = g_hl[buf] + (size_t)b * HID;
    const float* wl = W_lin + (size_t)w * HID;
    float s = 0.f;
#pragma unroll 4
    for (int k = lane; k < HID; k += 32) {
        float h = __bfloat162float(hh[k]) + __bfloat162float(hl[k]);
        s += h * wl[k];
    }
#pragma unroll
    for (int off = 16; off; off >>= 1)
        s += __shfl_down_sync(0xffffffffu, s, off);
    if (lane == 0)
        out[b * 10 + w] = s + b_lin[w];
}

// ---------------- launch ----------------
extern "C" void kernel_launch(void* const* d_in, const int* in_sizes, int n_in,
                              void* d_out, int out_size)
{
    const float* x     = (const float*)d_in[0];
    const float* h0    = (const float*)d_in[1];
    const float* c0    = (const float*)d_in[2];
    const float* W_ih  = (const float*)d_in[3];
    const float* W_hh  = (const float*)d_in[4];
    const float* b_ih  = (const float*)d_in[5];
    const float* b_hh  = (const float*)d_in[6];
    const float* W_lin = (const float*)d_in[7];
    const float* b_lin = (const float*)d_in[8];
    float* out = (float*)d_out;

    cudaFuncSetAttribute(lstm_persistent,
                         cudaFuncAttributeMaxDynamicSharedMemorySize, SMEM_TOTAL);

    reset_tickets_kernel<<<1, 128>>>();
    prepack_x_kernel<<<2048, 256>>>(x);
    prepack_w_kernel<<<1024, 256>>>(W_ih, W_hh, b_ih, b_hh);
    init_state_kernel<<<512, 512>>>(h0);

    dim3 grid(GATES / BN, B_SZ / BM);   // 16 x 8 = 128 CTAs (all resident)
    lstm_persistent<<<grid, 512, SMEM_TOTAL>>>(c0);

    // 256 steps -> final h is in buffer 0
    final_linear_kernel<<<B_SZ, dim3(32, 10)>>>(W_lin, b_lin, out, 0);
}

// round 10
// speedup vs baseline: 1.7297x; 1.6287x over previous
#include <cuda_runtime.h>
#include <cuda_fp16.h>
#include <math.h>
#include <stdint.h>

// ---------------- problem constants ----------------
#define B_SZ   1024
#define HID    512
#define INSZ   64
#define TSTEPS 256
#define GATES  2048              // 4*HID
#define KTOT   576               // INSZ + HID
#define XCOLS  (TSTEPS * INSZ)   // 16384

// ---------------- GEMM tiling ----------------
#define BM 128
#define BN 128
#define KTILE 64                 // 64 fp16 = 128 bytes per row
#define NJOBS 9                  // job j = K-chunk j (0 = x, 1..8 = h)
#define NROWCTA 16               // CTAs per row group (same blockIdx.y)

// SW128 swizzle (Swizzle<3,4,3>) on byte offsets within a tile
#define SWZ(o) ((o) ^ (((o) >> 3) & 0x70))

// dynamic smem layout (all tile bases 1024-aligned)
#define SOFF_BH    0                         // 9 x 16384 = 147456 (resident W_hi)
#define SOFF_A     147456                    // 2 x 16384 (double buffer)
#define SOFF_BL    (SOFF_A + 32768)          // 2 x 16384 (double buffer, W_lo stream)
#define SMEM_TOTAL (SOFF_BL + 32768)         // 212992

// ---------------- device scratch (no allocs allowed) ----------------
static __device__ __align__(256) __half g_x[(size_t)B_SZ * XCOLS];   // fp16 x
static __device__ __align__(256) __half g_Bh[GATES * KTOT];          // fp16(W), packed col = n*4+g
static __device__ __align__(256) __half g_Bl[GATES * KTOT];          // fp16(W - fp16(W))
static __device__ float  g_bias[GATES];
static __device__ __align__(256) __half g_h[2][B_SZ * HID];          // fp16 h (double buffer)
// per-row-group tickets, 128B apart; reset to 0 at the start of every launch
static __device__ unsigned long long g_row_ticket[8 * 16];

// ---------------- PTX helpers ----------------
__device__ __forceinline__ uint32_t smem_u32(const void* p) {
    uint32_t a;
    asm("{ .reg .u64 t; cvta.to.shared.u64 t, %1; cvt.u32.u64 %0, t; }"
        : "=r"(a) : "l"(p));
    return a;
}

__device__ __forceinline__ void cp16(uint32_t dst, const void* src) {
    asm volatile("cp.async.cg.shared.global [%0], [%1], 16;"
                 :: "r"(dst), "l"(src));
}
__device__ __forceinline__ void cp_commit() {
    asm volatile("cp.async.commit_group;" ::: "memory");
}
template<int N>
__device__ __forceinline__ void cp_wait() {
    asm volatile("cp.async.wait_group %0;" :: "n"(N) : "memory");
}

__device__ __forceinline__ void ldsm4(uint32_t* r, uint32_t addr) {
    asm volatile("ldmatrix.sync.aligned.m8n8.x4.shared.b16 {%0,%1,%2,%3}, [%4];"
                 : "=r"(r[0]), "=r"(r[1]), "=r"(r[2]), "=r"(r[3]) : "r"(addr));
}

__device__ __forceinline__ void mma16816(float* c, const uint32_t* a, const uint32_t* b) {
    asm volatile(
        "mma.sync.aligned.m16n8k16.row.col.f32.f16.f16.f32 "
        "{%0,%1,%2,%3}, {%4,%5,%6,%7}, {%8,%9}, {%0,%1,%2,%3};"
        : "+f"(c[0]), "+f"(c[1]), "+f"(c[2]), "+f"(c[3])
        : "r"(a[0]), "r"(a[1]), "r"(a[2]), "r"(a[3]), "r"(b[0]), "r"(b[1]));
}

__device__ __forceinline__ float fsig(float x) {
    float e = __expf(-x);
    return __fdividef(1.f, 1.f + e);
}
__device__ __forceinline__ float ftanh(float x) {
    return 2.f * fsig(2.f * x) - 1.f;
}

// ---------------- prepack kernels ----------------
__global__ void prepack_x_kernel(const float* __restrict__ x) {
    size_t idx = (size_t)blockIdx.x * blockDim.x + threadIdx.x;
    size_t stride = (size_t)gridDim.x * blockDim.x;
    const size_t total = (size_t)B_SZ * XCOLS;
    for (size_t i = idx; i < total; i += stride)
        g_x[i] = __float2half_rn(x[i]);
}

__global__ void prepack_w_kernel(const float* __restrict__ W_ih,
                                 const float* __restrict__ W_hh,
                                 const float* __restrict__ b_ih,
                                 const float* __restrict__ b_hh) {
    int idx = blockIdx.x * blockDim.x + threadIdx.x;
    int stride = gridDim.x * blockDim.x;
    const int total = GATES * KTOT;
    for (int i = idx; i < total; i += stride) {
        int col = i / KTOT;
        int k   = i - col * KTOT;
        int n = col >> 2, g = col & 3;
        int row = g * HID + n;
        float v = (k < INSZ) ? W_ih[row * INSZ + k] : W_hh[row * HID + (k - INSZ)];
        __half hi = __float2half_rn(v);
        g_Bh[i] = hi;
        g_Bl[i] = __float2half_rn(v - __half2float(hi));
    }
    for (int i = idx; i < GATES; i += stride) {
        int n = i >> 2, g = i & 3;
        int row = g * HID + n;
        g_bias[i] = b_ih[row] + b_hh[row];
    }
}

__global__ void init_state_kernel(const float* __restrict__ h0) {
    int idx = blockIdx.x * blockDim.x + threadIdx.x;
    int stride = gridDim.x * blockDim.x;
    for (int i = idx; i < B_SZ * HID; i += stride)
        g_h[0][i] = __float2half_rn(h0[i]);
}

__global__ void reset_tickets_kernel() {
    if (threadIdx.x < 8 * 16) g_row_ticket[threadIdx.x] = 0ULL;
}

// ---------------- persistent LSTM kernel (512 threads) ----------------
__global__ __launch_bounds__(512, 1)
void lstm_persistent(const float* __restrict__ c0g)
{
    extern __shared__ char smem[];
    const uint32_t sbase = smem_u32(smem);
    const int tid  = threadIdx.x;
    const int wid  = tid >> 5;
    const int lane = tid & 31;
    const int row0 = blockIdx.y * BM;   // batch base
    const int col0 = blockIdx.x * BN;   // packed gate col base
    const int wm = wid & 3;             // 0..3 (M)
    const int wn = wid >> 2;            // 0..3 (N)

    // loader mapping: 512 threads cover 128 rows x 128B (32B per thread)
    const int r     = tid >> 2;
    const int quart = tid & 3;
    const uint32_t rowoff = (uint32_t)r * 128 + (uint32_t)quart * 32;

    // ---- load resident B_hi (9 chunks, 147KB) ----
    {
        const size_t bb = (size_t)(col0 + r) * KTOT + (size_t)quart * 16;
        for (int sub = 0; sub < 9; ++sub) {
            uint32_t dst = sbase + SOFF_BH + sub * 16384;
#pragma unroll
            for (int c = 0; c < 2; ++c)
                cp16(dst + SWZ(rowoff + c * 16), g_Bh + bb + sub * KTILE + c * 8);
        }
        cp_commit();
    }

    // ---- per-thread epilogue constants: c state + bias in registers ----
    const int q  = lane & 3;
    const bool ev = (q & 1) == 0;
    float creg[2][4][2];
    float bb0[4], bb1[4];
#pragma unroll
    for (int nf = 0; nf < 4; ++nf) {
        int cb = wn * 32 + nf * 8 + q * 2;
        bb0[nf] = g_bias[col0 + cb];
        bb1[nf] = g_bias[col0 + cb + 1];
#pragma unroll
        for (int mf = 0; mf < 2; ++mf)
#pragma unroll
            for (int rs = 0; rs < 2; ++rs) {
                int n = (col0 + cb) >> 2;
                int b = row0 + wm * 32 + (lane >> 2) + mf * 16 + rs * 8;
                creg[mf][nf][rs] = c0g[(size_t)b * HID + n];
            }
    }

    // fragment addressing constants
    const int lane7 = lane & 7;
    const int arow  = wm * 32 + ((lane >> 3) & 1) * 8 + lane7;   // + mf*16
    const int ach   = (lane >> 4) & 1;
    const int brow  = wn * 32 + ((lane >> 4) & 1) * 8 + lane7;   // + p*16
    const int bch   = (lane >> 3) & 1;

    const uint32_t sA0  = sbase + SOFF_A;
    const uint32_t sBL0 = sbase + SOFF_BL;

    // job j = K-chunk j: A(j) x (B_hi[j] resident + B_lo[j] streamed)
    // A buffer = j & 1, BL buffer = j & 1; one commit group per job.
    auto issue_job = [&](int jid, int t, int buf) {
        const __half* __restrict__ Asrc;
        size_t abase;
        if (jid == 0) {   // x part (h-independent)
            Asrc  = g_x;
            abase = (size_t)(row0 + r) * XCOLS + (size_t)t * INSZ;
        } else {
            Asrc  = g_h[buf];
            abase = (size_t)(row0 + r) * HID + (size_t)(jid - 1) * KTILE;
        }
        abase += (size_t)quart * 16;
        const uint32_t bo = (uint32_t)(jid & 1) * 16384;
#pragma unroll
        for (int c = 0; c < 2; ++c)
            cp16(sA0 + bo + SWZ(rowoff + c * 16), Asrc + abase + c * 8);
        const size_t bbase = (size_t)(col0 + r) * KTOT
                             + (size_t)jid * KTILE + (size_t)quart * 16;
#pragma unroll
        for (int c = 0; c < 2; ++c)
            cp16(sBL0 + bo + SWZ(rowoff + c * 16), g_Bl + bbase + c * 8);
        cp_commit();
    };

    float acc[2][4][4];

    // MMA of one job: 4 kk slices, two B passes (hi resident, lo streamed)
    auto mma_job = [&](int j) {
        const uint32_t sA  = sA0 + (uint32_t)(j & 1) * 16384;
        const uint32_t sBH = sbase + SOFF_BH + (uint32_t)j * 16384;
        const uint32_t sBL = sBL0 + (uint32_t)(j & 1) * 16384;
#pragma unroll
        for (int kk = 0; kk < 4; ++kk) {
            uint32_t af[2][4];
#pragma unroll
            for (int mf = 0; mf < 2; ++mf)
                ldsm4(af[mf], sA + SWZ((uint32_t)(arow + mf * 16) * 128
                                       + (uint32_t)(kk * 2 + ach) * 16));
            {
                uint32_t bf[4][2];
#pragma unroll
                for (int p = 0; p < 2; ++p) {
                    uint32_t rr[4];
                    ldsm4(rr, sBH + SWZ((uint32_t)(brow + p * 16) * 128
                                        + (uint32_t)(kk * 2 + bch) * 16));
                    bf[p * 2 + 0][0] = rr[0]; bf[p * 2 + 0][1] = rr[1];
                    bf[p * 2 + 1][0] = rr[2]; bf[p * 2 + 1][1] = rr[3];
                }
#pragma unroll
                for (int mf = 0; mf < 2; ++mf)
#pragma unroll
                    for (int nf = 0; nf < 4; ++nf)
                        mma16816(acc[mf][nf], af[mf], bf[nf]);
            }
            {
                uint32_t bf[4][2];
#pragma unroll
                for (int p = 0; p < 2; ++p) {
                    uint32_t rr[4];
                    ldsm4(rr, sBL + SWZ((uint32_t)(brow + p * 16) * 128
                                        + (uint32_t)(kk * 2 + bch) * 16));
                    bf[p * 2 + 0][0] = rr[0]; bf[p * 2 + 0][1] = rr[1];
                    bf[p * 2 + 1][0] = rr[2]; bf[p * 2 + 1][1] = rr[3];
                }
#pragma unroll
                for (int mf = 0; mf < 2; ++mf)
#pragma unroll
                    for (int nf = 0; nf < 4; ++nf)
                        mma16816(acc[mf][nf], af[mf], bf[nf]);
            }
        }
    };

    // prologue: x job of step 0 (after BH group)
    issue_job(0, 0, 0);
    cp_wait<0>();       // BH + G(0) resident
    __syncthreads();

    for (int t = 0; t < TSTEPS; ++t) {
        const int buf  = t & 1;
        const int nbuf = buf ^ 1;

#pragma unroll
        for (int mf = 0; mf < 2; ++mf)
#pragma unroll
            for (int nf = 0; nf < 4; ++nf)
#pragma unroll
                for (int u = 0; u < 4; ++u) acc[mf][nf][u] = 0.f;

        // ---- job 0 (x): barrier-independent, hides the row-group spin ----
        cp_wait<0>();
        __syncthreads();
        mma_job(0);

        // ---- row-group barrier: h[t] visible (overlapped by job-0 MMA) ----
        if (t > 0 && tid == 0) {
            const unsigned long long target =
                (unsigned long long)t * (unsigned long long)NROWCTA;
            unsigned long long cur;
            unsigned long long* p = &g_row_ticket[blockIdx.y * 16];
            do {
                asm volatile("ld.acquire.gpu.u64 %0, [%1];" : "=l"(cur) : "l"(p));
            } while (cur < target);
        }
        __syncthreads();   // orders job-0 MMA before h reads / buffer reuse

        // h now safe to read
        issue_job(1, t, buf);

        // ---- jobs 1..8 ----
        for (int j = 1; j < NJOBS; ++j) {
            cp_wait<0>();
            __syncthreads();
            if (j + 1 < NJOBS) issue_job(j + 1, t, buf);
            mma_job(j);
        }

        // ---- fused LSTM epilogue ----
#pragma unroll
        for (int mf = 0; mf < 2; ++mf) {
#pragma unroll
            for (int nf = 0; nf < 4; ++nf) {
                const int cb = wn * 32 + nf * 8 + q * 2;
#pragma unroll
                for (int rs = 0; rs < 2; ++rs) {
                    float v0 = acc[mf][nf][rs * 2 + 0] + bb0[nf];
                    float v1 = acc[mf][nf][rs * 2 + 1] + bb1[nf];
                    // even lanes: x0=sig(i), x1=sig(f); odd: x0=tanh(g), x1=sig(o)
                    float x0 = ev ? fsig(v0) : ftanh(v0);
                    float x1 = fsig(v1);
                    float y0 = __shfl_xor_sync(0xffffffffu, x0, 1);
                    float y1 = __shfl_xor_sync(0xffffffffu, x1, 1);
                    if (ev) {
                        const int n = (col0 + cb) >> 2;
                        const int b = row0 + wm * 32 + (lane >> 2) + mf * 16 + rs * 8;
                        const size_t idx = (size_t)b * HID + n;
                        float cn = x1 * creg[mf][nf][rs] + x0 * y0;   // f*c + i*g
                        creg[mf][nf][rs] = cn;
                        float hn = y1 * ftanh(cn);                    // o * tanh(c)
                        g_h[nbuf][idx] = __float2half_rn(hn);
                    }
                }
            }
        }

        // post arrival for next step's row barrier + pre-issue next x job
        if (t + 1 < TSTEPS) {
            __syncthreads();   // h stores + mma(8) done block-wide
            if (tid == 0) {
                unsigned long long one = 1ULL;
                asm volatile("red.release.gpu.global.add.u64 [%0], %1;"
                             :: "l"(&g_row_ticket[blockIdx.y * 16]), "l"(one)
                             : "memory");
            }
            issue_job(0, t + 1, nbuf);
        }
    }
}

// ---------------- final linear ----------------
__global__ void final_linear_kernel(const float* __restrict__ W_lin,
                                    const float* __restrict__ b_lin,
                                    float* __restrict__ out, int buf)
{
    int b = blockIdx.x;
    int w = threadIdx.y;      // 0..9
    int lane = threadIdx.x;   // 0..31
    const __half* h = g_h[buf] + (size_t)b * HID;
    const float* wl = W_lin + (size_t)w * HID;
    float s = 0.f;
#pragma unroll 4
    for (int k = lane; k < HID; k += 32)
        s += __half2float(h[k]) * wl[k];
#pragma unroll
    for (int off = 16; off; off >>= 1)
        s += __shfl_down_sync(0xffffffffu, s, off);
    if (lane == 0)
        out[b * 10 + w] = s + b_lin[w];
}

// ---------------- launch ----------------
extern "C" void kernel_launch(void* const* d_in, const int* in_sizes, int n_in,
                              void* d_out, int out_size)
{
    const float* x     = (const float*)d_in[0];
    const float* h0    = (const float*)d_in[1];
    const float* c0    = (const float*)d_in[2];
    const float* W_ih  = (const float*)d_in[3];
    const float* W_hh  = (const float*)d_in[4];
    const float* b_ih  = (const float*)d_in[5];
    const float* b_hh  = (const float*)d_in[6];
    const float* W_lin = (const float*)d_in[7];
    const float* b_lin = (const float*)d_in[8];
    float* out = (float*)d_out;

    cudaFuncSetAttribute(lstm_persistent,
                         cudaFuncAttributeMaxDynamicSharedMemorySize, SMEM_TOTAL);

    reset_tickets_kernel<<<1, 128>>>();
    prepack_x_kernel<<<2048, 256>>>(x);
    prepack_w_kernel<<<1024, 256>>>(W_ih, W_hh, b_ih, b_hh);
    init_state_kernel<<<512, 512>>>(h0);

    dim3 grid(GATES / BN, B_SZ / BM);   // 16 x 8 = 128 CTAs (all resident)
    lstm_persistent<<<grid, 512, SMEM_TOTAL>>>(c0);

    // 256 steps -> final h is in buffer 0
    final_linear_kernel<<<B_SZ, dim3(32, 10)>>>(W_lin, b_lin, out, 0);
}

// round 11
// speedup vs baseline: 2.8700x; 1.6592x over previous
#include <cuda_runtime.h>
#include <cuda_fp16.h>
#include <math.h>
#include <stdint.h>

// ---------------- problem constants ----------------
#define B_SZ   1024
#define HID    512
#define INSZ   64
#define TSTEPS 256
#define GATES  2048              // 4*HID
#define KTOT   576               // INSZ + HID
#define XCOLS  (TSTEPS * INSZ)   // 16384

// ---------------- GEMM tiling ----------------
#define BM 128
#define BN 128
#define KTILE 64                 // 64 fp16 = 128 bytes per row
#define NJOBS 9                  // job j = K-chunk j (0 = x, 1..8 = h)
#define NROWCTA 16               // CTAs per row group (same blockIdx.y)

// SW128 swizzle (Swizzle<3,4,3>) on byte offsets within a tile
#define SWZ(o) ((o) ^ (((o) >> 3) & 0x70))

// dynamic smem layout (all tile bases 1024-aligned)
#define SOFF_BH    0                         // 9 x 16384 = 147456 (resident W)
#define SOFF_A     147456                    // 3 x 16384 (triple buffer)
#define SMEM_TOTAL (SOFF_A + 49152)          // 196608

// ---------------- device scratch (no allocs allowed) ----------------
static __device__ __align__(256) __half g_x[(size_t)B_SZ * XCOLS];   // fp16 x
static __device__ __align__(256) __half g_Bh[GATES * KTOT];          // fp16(W), packed col = n*4+g
static __device__ float  g_bias[GATES];
static __device__ __align__(256) __half g_h[2][B_SZ * HID];          // fp16 h (double buffer)
// per-row-group tickets, 128B apart; reset to 0 at the start of every launch
static __device__ unsigned long long g_row_ticket[8 * 16];

// ---------------- PTX helpers ----------------
__device__ __forceinline__ uint32_t smem_u32(const void* p) {
    uint32_t a;
    asm("{ .reg .u64 t; cvta.to.shared.u64 t, %1; cvt.u32.u64 %0, t; }"
        : "=r"(a) : "l"(p));
    return a;
}

__device__ __forceinline__ void cp16(uint32_t dst, const void* src) {
    asm volatile("cp.async.cg.shared.global [%0], [%1], 16;"
                 :: "r"(dst), "l"(src));
}
__device__ __forceinline__ void cp_commit() {
    asm volatile("cp.async.commit_group;" ::: "memory");
}
template<int N>
__device__ __forceinline__ void cp_wait() {
    asm volatile("cp.async.wait_group %0;" :: "n"(N) : "memory");
}

__device__ __forceinline__ void ldsm4(uint32_t* r, uint32_t addr) {
    asm volatile("ldmatrix.sync.aligned.m8n8.x4.shared.b16 {%0,%1,%2,%3}, [%4];"
                 : "=r"(r[0]), "=r"(r[1]), "=r"(r[2]), "=r"(r[3]) : "r"(addr));
}

__device__ __forceinline__ void mma16816(float* c, const uint32_t* a, const uint32_t* b) {
    asm volatile(
        "mma.sync.aligned.m16n8k16.row.col.f32.f16.f16.f32 "
        "{%0,%1,%2,%3}, {%4,%5,%6,%7}, {%8,%9}, {%0,%1,%2,%3};"
        : "+f"(c[0]), "+f"(c[1]), "+f"(c[2]), "+f"(c[3])
        : "r"(a[0]), "r"(a[1]), "r"(a[2]), "r"(a[3]), "r"(b[0]), "r"(b[1]));
}

__device__ __forceinline__ float fsig(float x) {
    float e = __expf(-x);
    return __fdividef(1.f, 1.f + e);
}
__device__ __forceinline__ float ftanh(float x) {
    return 2.f * fsig(2.f * x) - 1.f;
}

// ---------------- prepack kernels ----------------
__global__ void prepack_x_kernel(const float* __restrict__ x) {
    size_t idx = (size_t)blockIdx.x * blockDim.x + threadIdx.x;
    size_t stride = (size_t)gridDim.x * blockDim.x;
    const size_t total = (size_t)B_SZ * XCOLS;
    for (size_t i = idx; i < total; i += stride)
        g_x[i] = __float2half_rn(x[i]);
}

__global__ void prepack_w_kernel(const float* __restrict__ W_ih,
                                 const float* __restrict__ W_hh,
                                 const float* __restrict__ b_ih,
                                 const float* __restrict__ b_hh) {
    int idx = blockIdx.x * blockDim.x + threadIdx.x;
    int stride = gridDim.x * blockDim.x;
    const int total = GATES * KTOT;
    for (int i = idx; i < total; i += stride) {
        int col = i / KTOT;
        int k   = i - col * KTOT;
        int n = col >> 2, g = col & 3;
        int row = g * HID + n;
        float v = (k < INSZ) ? W_ih[row * INSZ + k] : W_hh[row * HID + (k - INSZ)];
        g_Bh[i] = __float2half_rn(v);
    }
    for (int i = idx; i < GATES; i += stride) {
        int n = i >> 2, g = i & 3;
        int row = g * HID + n;
        g_bias[i] = b_ih[row] + b_hh[row];
    }
}

__global__ void init_state_kernel(const float* __restrict__ h0) {
    int idx = blockIdx.x * blockDim.x + threadIdx.x;
    int stride = gridDim.x * blockDim.x;
    for (int i = idx; i < B_SZ * HID; i += stride)
        g_h[0][i] = __float2half_rn(h0[i]);
}

__global__ void reset_tickets_kernel() {
    if (threadIdx.x < 8 * 16) g_row_ticket[threadIdx.x] = 0ULL;
}

// ---------------- persistent LSTM kernel (512 threads) ----------------
__global__ __launch_bounds__(512, 1)
void lstm_persistent(const float* __restrict__ c0g)
{
    extern __shared__ char smem[];
    const uint32_t sbase = smem_u32(smem);
    const int tid  = threadIdx.x;
    const int wid  = tid >> 5;
    const int lane = tid & 31;
    const int row0 = blockIdx.y * BM;   // batch base
    const int col0 = blockIdx.x * BN;   // packed gate col base
    const int wm = wid & 3;             // 0..3 (M)
    const int wn = wid >> 2;            // 0..3 (N)

    // loader mapping: 512 threads cover 128 rows x 128B (32B per thread)
    const int r     = tid >> 2;
    const int quart = tid & 3;
    const uint32_t rowoff = (uint32_t)r * 128 + (uint32_t)quart * 32;

    // ---- load resident W (9 chunks, 147KB) ----
    {
        const size_t bb = (size_t)(col0 + r) * KTOT + (size_t)quart * 16;
        for (int sub = 0; sub < 9; ++sub) {
            uint32_t dst = sbase + SOFF_BH + sub * 16384;
#pragma unroll
            for (int c = 0; c < 2; ++c)
                cp16(dst + SWZ(rowoff + c * 16), g_Bh + bb + sub * KTILE + c * 8);
        }
        cp_commit();
    }

    // ---- per-thread epilogue constants: c state + bias in registers ----
    const int q  = lane & 3;
    const bool ev = (q & 1) == 0;
    float creg[2][4][2];
    float bb0[4], bb1[4];
#pragma unroll
    for (int nf = 0; nf < 4; ++nf) {
        int cb = wn * 32 + nf * 8 + q * 2;
        bb0[nf] = g_bias[col0 + cb];
        bb1[nf] = g_bias[col0 + cb + 1];
#pragma unroll
        for (int mf = 0; mf < 2; ++mf)
#pragma unroll
            for (int rs = 0; rs < 2; ++rs) {
                int n = (col0 + cb) >> 2;
                int b = row0 + wm * 32 + (lane >> 2) + mf * 16 + rs * 8;
                creg[mf][nf][rs] = c0g[(size_t)b * HID + n];
            }
    }

    // fragment addressing constants
    const int lane7 = lane & 7;
    const int arow  = wm * 32 + ((lane >> 3) & 1) * 8 + lane7;   // + mf*16
    const int ach   = (lane >> 4) & 1;
    const int brow  = wn * 32 + ((lane >> 4) & 1) * 8 + lane7;   // + p*16
    const int bch   = (lane >> 3) & 1;

    const uint32_t sA0 = sbase + SOFF_A;

    // job j = K-chunk j: A(j) x B[j] (resident). A buffer = j % 3 (triple).
    auto issue_job = [&](int jid, int t, int buf) {
        const __half* __restrict__ Asrc;
        size_t abase;
        if (jid == 0) {   // x part (h-independent)
            Asrc  = g_x;
            abase = (size_t)(row0 + r) * XCOLS + (size_t)t * INSZ;
        } else {
            Asrc  = g_h[buf];
            abase = (size_t)(row0 + r) * HID + (size_t)(jid - 1) * KTILE;
        }
        abase += (size_t)quart * 16;
        const uint32_t ao = (uint32_t)(jid % 3) * 16384;
#pragma unroll
        for (int c = 0; c < 2; ++c)
            cp16(sA0 + ao + SWZ(rowoff + c * 16), Asrc + abase + c * 8);
        cp_commit();
    };

    float acc[2][4][4];

    // MMA of one job: 4 kk slices against resident W chunk j
    auto mma_job = [&](int j) {
        const uint32_t sA  = sA0 + (uint32_t)(j % 3) * 16384;
        const uint32_t sBH = sbase + SOFF_BH + (uint32_t)j * 16384;
#pragma unroll
        for (int kk = 0; kk < 4; ++kk) {
            uint32_t af[2][4];
#pragma unroll
            for (int mf = 0; mf < 2; ++mf)
                ldsm4(af[mf], sA + SWZ((uint32_t)(arow + mf * 16) * 128
                                       + (uint32_t)(kk * 2 + ach) * 16));
            uint32_t bf[4][2];
#pragma unroll
            for (int p = 0; p < 2; ++p) {
                uint32_t rr[4];
                ldsm4(rr, sBH + SWZ((uint32_t)(brow + p * 16) * 128
                                    + (uint32_t)(kk * 2 + bch) * 16));
                bf[p * 2 + 0][0] = rr[0]; bf[p * 2 + 0][1] = rr[1];
                bf[p * 2 + 1][0] = rr[2]; bf[p * 2 + 1][1] = rr[3];
            }
#pragma unroll
            for (int mf = 0; mf < 2; ++mf)
#pragma unroll
                for (int nf = 0; nf < 4; ++nf)
                    mma16816(acc[mf][nf], af[mf], bf[nf]);
        }
    };

    // prologue: x job of step 0 (after W group)
    issue_job(0, 0, 0);

    for (int t = 0; t < TSTEPS; ++t) {
        const int buf  = t & 1;
        const int nbuf = buf ^ 1;

#pragma unroll
        for (int mf = 0; mf < 2; ++mf)
#pragma unroll
            for (int nf = 0; nf < 4; ++nf)
#pragma unroll
                for (int u = 0; u < 4; ++u) acc[mf][nf][u] = 0.f;

        // ---- job 0 (x): barrier-independent, hides the row-group spin ----
        cp_wait<0>();           // x tile (and W group at t=0) resident
        __syncthreads();
        mma_job(0);

        // ---- row-group barrier: h[t] visible (overlapped by job-0 MMA) ----
        if (t > 0 && tid == 0) {
            const unsigned long long target =
                (unsigned long long)t * (unsigned long long)NROWCTA;
            unsigned long long cur;
            unsigned long long* p = &g_row_ticket[blockIdx.y * 16];
            do {
                asm volatile("ld.acquire.gpu.u64 %0, [%1];" : "=l"(cur) : "l"(p));
            } while (cur < target);
        }
        __syncthreads();   // orders job-0 MMA before h reads / buffer reuse

        // h now safe to read: prime lookahead of 2
        issue_job(1, t, buf);
        issue_job(2, t, buf);

        // ---- jobs 1..8: lookahead-2 pipeline ----
        for (int j = 1; j < NJOBS; ++j) {
            cp_wait<1>();       // job j's group arrived (<=1 pending: j+1 or x)
            __syncthreads();
            if (j + 2 < NJOBS) {
                issue_job(j + 2, t, buf);
            } else if (j + 2 == NJOBS) {
                // j == 7: pre-issue next step's x job (or empty group to keep
                // the wait-depth invariant on the final step)
                if (t + 1 < TSTEPS) issue_job(0, t + 1, nbuf);
                else                cp_commit();
            }
            mma_job(j);
        }

        // ---- fused LSTM epilogue ----
#pragma unroll
        for (int mf = 0; mf < 2; ++mf) {
#pragma unroll
            for (int nf = 0; nf < 4; ++nf) {
                const int cb = wn * 32 + nf * 8 + q * 2;
#pragma unroll
                for (int rs = 0; rs < 2; ++rs) {
                    float v0 = acc[mf][nf][rs * 2 + 0] + bb0[nf];
                    float v1 = acc[mf][nf][rs * 2 + 1] + bb1[nf];
                    // even lanes: x0=sig(i), x1=sig(f); odd: x0=tanh(g), x1=sig(o)
                    float x0 = ev ? fsig(v0) : ftanh(v0);
                    float x1 = fsig(v1);
                    float y0 = __shfl_xor_sync(0xffffffffu, x0, 1);
                    float y1 = __shfl_xor_sync(0xffffffffu, x1, 1);
                    if (ev) {
                        const int n = (col0 + cb) >> 2;
                        const int b = row0 + wm * 32 + (lane >> 2) + mf * 16 + rs * 8;
                        const size_t idx = (size_t)b * HID + n;
                        float cn = x1 * creg[mf][nf][rs] + x0 * y0;   // f*c + i*g
                        creg[mf][nf][rs] = cn;
                        float hn = y1 * ftanh(cn);                    // o * tanh(c)
                        g_h[nbuf][idx] = __float2half_rn(hn);
                    }
                }
            }
        }

        // post arrival for next step's row barrier (release semantics)
        if (t + 1 < TSTEPS) {
            __syncthreads();   // h stores complete block-wide
            if (tid == 0) {
                unsigned long long one = 1ULL;
                asm volatile("red.release.gpu.global.add.u64 [%0], %1;"
                             :: "l"(&g_row_ticket[blockIdx.y * 16]), "l"(one)
                             : "memory");
            }
        }
    }
}

// ---------------- final linear ----------------
__global__ void final_linear_kernel(const float* __restrict__ W_lin,
                                    const float* __restrict__ b_lin,
                                    float* __restrict__ out, int buf)
{
    int b = blockIdx.x;
    int w = threadIdx.y;      // 0..9
    int lane = threadIdx.x;   // 0..31
    const __half* h = g_h[buf] + (size_t)b * HID;
    const float* wl = W_lin + (size_t)w * HID;
    float s = 0.f;
#pragma unroll 4
    for (int k = lane; k < HID; k += 32)
        s += __half2float(h[k]) * wl[k];
#pragma unroll
    for (int off = 16; off; off >>= 1)
        s += __shfl_down_sync(0xffffffffu, s, off);
    if (lane == 0)
        out[b * 10 + w] = s + b_lin[w];
}

// ---------------- launch ----------------
extern "C" void kernel_launch(void* const* d_in, const int* in_sizes, int n_in,
                              void* d_out, int out_size)
{
    const float* x     = (const float*)d_in[0];
    const float* h0    = (const float*)d_in[1];
    const float* c0    = (const float*)d_in[2];
    const float* W_ih  = (const float*)d_in[3];
    const float* W_hh  = (const float*)d_in[4];
    const float* b_ih  = (const float*)d_in[5];
    const float* b_hh  = (const float*)d_in[6];
    const float* W_lin = (const float*)d_in[7];
    const float* b_lin = (const float*)d_in[8];
    float* out = (float*)d_out;

    cudaFuncSetAttribute(lstm_persistent,
                         cudaFuncAttributeMaxDynamicSharedMemorySize, SMEM_TOTAL);

    reset_tickets_kernel<<<1, 128>>>();
    prepack_x_kernel<<<2048, 256>>>(x);
    prepack_w_kernel<<<1024, 256>>>(W_ih, W_hh, b_ih, b_hh);
    init_state_kernel<<<512, 512>>>(h0);

    dim3 grid(GATES / BN, B_SZ / BM);   // 16 x 8 = 128 CTAs (all resident)
    lstm_persistent<<<grid, 512, SMEM_TOTAL>>>(c0);

    // 256 steps -> final h is in buffer 0
    final_linear_kernel<<<B_SZ, dim3(32, 10)>>>(W_lin, b_lin, out, 0);
}